// round 15
// baseline (speedup 1.0000x reference)
#include <cuda_runtime.h>
#include <math_constants.h>

#define HW      16384
#define WDIM    128
#define KTOP    16
#define THREADS 256
#define NWARP   (THREADS / 32)
#define NITER   (HW / 4 / THREADS)   // 16 float4s per thread
#define GROUP   8                    // front-batched loads per group
#define CAP     1024                 // candidate buffer (expected ~22 used)

__device__ __forceinline__ unsigned f2ord(float f) {
    unsigned u = __float_as_uint(f);
    return u ^ ((unsigned)((int)u >> 31) | 0x80000000u);
}
__device__ __forceinline__ float ord2f(unsigned s) {
    unsigned u = (s & 0x80000000u) ? (s ^ 0x80000000u) : ~s;
    return __uint_as_float(u);
}

__global__ void __launch_bounds__(THREADS, 4)
topk_l2_kernel(const float* __restrict__ x,
               float* __restrict__ out_val,    // [rows,16]
               float2* __restrict__ out_coor)  // [rows,16] of (h,w)
{
    const int row = blockIdx.x;
    const int tid = threadIdx.x;
    const int lane = tid & 31;
    const int wid  = tid >> 5;

    const float4* __restrict__ xp =
        reinterpret_cast<const float4*>(x) + (size_t)row * (HW / 4);

    // ---------------- Phase A: ss + thread-max, 8-deep load staging --------
    unsigned long long ssA = 0ull, ssB = 0ull;   // packed f32x2 accumulators
    float mx0 = -CUDART_INF_F, mx1 = -CUDART_INF_F;

#pragma unroll
    for (int g = 0; g < NITER / GROUP; g++) {
        float4 buf[GROUP];
#pragma unroll
        for (int j = 0; j < GROUP; j++)          // front-batched LDG.128 x8
            buf[j] = xp[tid + (g * GROUP + j) * THREADS];
#pragma unroll
        for (int j = 0; j < GROUP; j++) {
            float4 v = buf[j];
            unsigned long long p01, p23;
            asm("mov.b64 %0, {%1,%2};" : "=l"(p01) : "f"(v.x), "f"(v.y));
            asm("mov.b64 %0, {%1,%2};" : "=l"(p23) : "f"(v.z), "f"(v.w));
            asm("fma.rn.f32x2 %0, %1, %1, %0;" : "+l"(ssA) : "l"(p01));
            asm("fma.rn.f32x2 %0, %1, %1, %0;" : "+l"(ssB) : "l"(p23));
            mx0 = fmaxf(mx0, fmaxf(v.x, v.y));
            mx1 = fmaxf(mx1, fmaxf(v.z, v.w));
        }
    }

    float sa0, sa1, sb0, sb1;
    asm("mov.b64 {%0,%1}, %2;" : "=f"(sa0), "=f"(sa1) : "l"(ssA));
    asm("mov.b64 {%0,%1}, %2;" : "=f"(sb0), "=f"(sb1) : "l"(ssB));
    float ssv = (sa0 + sa1) + (sb0 + sb1);

    const unsigned key = f2ord(fmaxf(mx0, mx1));

    // ---- warp reduce: sum(ss) and top-2 of thread-max keys ----------------
    unsigned k1 = key, k2 = 0u;
#pragma unroll
    for (int off = 16; off > 0; off >>= 1) {
        ssv += __shfl_xor_sync(0xFFFFFFFFu, ssv, off);
        unsigned o1 = __shfl_xor_sync(0xFFFFFFFFu, k1, off);
        unsigned o2 = __shfl_xor_sync(0xFFFFFFFFu, k2, off);
        unsigned hi = max(k1, o1);
        unsigned se = max(min(k1, o1), max(k2, o2));
        k1 = hi; k2 = se;
    }

    // ---------------- shared state ----------------------------------------
    __shared__ unsigned long long cand_s[CAP];
    __shared__ float    wss[NWARP];
    __shared__ unsigned w2nd[NWARP];
    __shared__ int ccnt;

    if (lane == 0) { wss[wid] = ssv; w2nd[wid] = k2; }
    if (tid == 0) ccnt = 0;
    __syncthreads();   // barrier #1

    // tau = min over warps of (warp's 2nd-largest thread-max)
    // => >=2 elements per warp >= tau => >=16 elements >= tau (exactness)
    unsigned tau_ord = w2nd[0];
    float tot = wss[0];
#pragma unroll
    for (int w = 1; w < NWARP; w++) {
        tau_ord = min(tau_ord, w2nd[w]);
        tot += wss[w];
    }
    const float tau   = ord2f(tau_ord);
    const float scale = rsqrtf(fmaxf(tot, 1e-12f));

    // ---------------- Phase B: sparse rescan (L1/L2 hits) ------------------
    if (key >= tau_ord) {          // ~35 of 256 threads
#pragma unroll
        for (int it = 0; it < NITER; it++) {
            float4 v = xp[tid + it * THREADS];
            int base = (tid + it * THREADS) * 4;
#pragma unroll
            for (int e = 0; e < 4; e++) {
                float f = (e == 0) ? v.x : (e == 1) ? v.y : (e == 2) ? v.z : v.w;
                if (f >= tau) {
                    unsigned long long kk =
                        ((unsigned long long)f2ord(f) << 32) |
                        (unsigned)(~(unsigned)(base + e));
                    int pos = atomicAdd(&ccnt, 1);
                    if (pos < CAP) cand_s[pos] = kk;
                }
            }
        }
    }
    __syncthreads();   // barrier #2

    // ---------------- parallel rank-select + write -------------------------
    const int C = min(ccnt, CAP);   // >= 16 guaranteed
    for (int i = tid; i < C; i += THREADS) {
        unsigned long long mine = cand_s[i];
        int rank = 0;
        for (int j = 0; j < C; j++)
            rank += (cand_s[j] > mine);   // keys unique (index embedded)
        if (rank < KTOP) {
            float val = ord2f((unsigned)(mine >> 32)) * scale;
            int idx = (int)(~(unsigned)(mine & 0xFFFFFFFFull));
            out_val[(size_t)row * KTOP + rank] = val;
            out_coor[(size_t)row * KTOP + rank] =
                make_float2((float)(idx >> 7), (float)(idx & (WDIM - 1)));
        }
    }
}

extern "C" void kernel_launch(void* const* d_in, const int* in_sizes, int n_in,
                              void* d_out, int out_size)
{
    const float* x = (const float*)d_in[0];
    int n = in_sizes[0];               // 16*256*128*128
    int rows = n / HW;                 // 4096

    float*  out_val  = (float*)d_out;
    float2* out_coor = (float2*)(out_val + (size_t)rows * KTOP);

    topk_l2_kernel<<<rows, THREADS>>>(x, out_val, out_coor);
}

// round 17
// speedup vs baseline: 1.1936x; 1.1936x over previous
#include <cuda_runtime.h>
#include <math_constants.h>
#include <cstdint>

#define HW      16384
#define WDIM    128
#define KTOP    16
#define THREADS 256
#define NWARP   (THREADS / 32)
#define CAP     1024
#define NSTAGE  4
#define CHUNK_FLOATS 2048                 // 8 KB per chunk
#define CHUNK_BYTES  (CHUNK_FLOATS * 4)
#define NCHUNK  (HW / CHUNK_FLOATS)       // 8
#define VPT     (CHUNK_FLOATS / 4 / THREADS)  // 2 float4 per thread per chunk

__device__ __forceinline__ unsigned f2ord(float f) {
    unsigned u = __float_as_uint(f);
    return u ^ ((unsigned)((int)u >> 31) | 0x80000000u);
}
__device__ __forceinline__ float ord2f(unsigned s) {
    unsigned u = (s & 0x80000000u) ? (s ^ 0x80000000u) : ~s;
    return __uint_as_float(u);
}
__device__ __forceinline__ unsigned int s2u(const void* p) {
    return (unsigned int)__cvta_generic_to_shared(p);
}
__device__ __forceinline__ void mbar_init(unsigned int a, unsigned int cnt) {
    asm volatile("mbarrier.init.shared.b64 [%0], %1;" :: "r"(a), "r"(cnt) : "memory");
}
__device__ __forceinline__ void mbar_expect_tx(unsigned int a, unsigned int bytes) {
    asm volatile("mbarrier.arrive.expect_tx.shared.b64 _, [%0], %1;"
                 :: "r"(a), "r"(bytes) : "memory");
}
__device__ __forceinline__ void bulk_g2s(unsigned int dst, const void* src,
                                         unsigned int bytes, unsigned int mbar) {
    asm volatile(
        "cp.async.bulk.shared::cluster.global.mbarrier::complete_tx::bytes "
        "[%0], [%1], %2, [%3];"
        :: "r"(dst), "l"(src), "r"(bytes), "r"(mbar) : "memory");
}
__device__ __forceinline__ void mbar_wait(unsigned int a, unsigned int parity) {
    asm volatile(
        "{\n\t.reg .pred P;\n\t"
        "W%=:\n\t"
        "mbarrier.try_wait.parity.acquire.cta.shared::cta.b64 P, [%0], %1, 0x989680;\n\t"
        "@P bra D%=;\n\t"
        "bra W%=;\n\t"
        "D%=:\n\t}"
        :: "r"(a), "r"(parity) : "memory");
}

__global__ void __launch_bounds__(THREADS, 5)
topk_l2_kernel(const float* __restrict__ x,
               float* __restrict__ out_val,    // [rows,16]
               float2* __restrict__ out_coor)  // [rows,16] of (h,w)
{
    const int row = blockIdx.x;
    const int tid = threadIdx.x;
    const int lane = tid & 31;
    const int wid  = tid >> 5;

    const float* __restrict__ rowp = x + (size_t)row * HW;

    __shared__ __align__(16) float4 stage[NSTAGE][CHUNK_FLOATS / 4];
    __shared__ unsigned long long mbar[NSTAGE];
    __shared__ unsigned long long cand_s[CAP];
    __shared__ float    wss[NWARP];
    __shared__ unsigned w2nd[NWARP];
    __shared__ int ccnt;

    // ---- init mbarriers + prologue loads (producer = tid 0) ----
    if (tid == 0) {
        ccnt = 0;
#pragma unroll
        for (int s = 0; s < NSTAGE; s++) mbar_init(s2u(&mbar[s]), 1);
        asm volatile("fence.proxy.async.shared::cta;" ::: "memory");
#pragma unroll
        for (int s = 0; s < NSTAGE; s++) {
            mbar_expect_tx(s2u(&mbar[s]), CHUNK_BYTES);
            bulk_g2s(s2u(&stage[s][0]), rowp + s * CHUNK_FLOATS,
                     CHUNK_BYTES, s2u(&mbar[s]));
        }
    }
    __syncthreads();

    // ---------------- Phase A: pipelined consume (ss + thread-max) ---------
    unsigned long long ssA = 0ull, ssB = 0ull;   // packed f32x2 accumulators
    float mx0 = -CUDART_INF_F, mx1 = -CUDART_INF_F;

#pragma unroll
    for (int c = 0; c < NCHUNK; c++) {
        const int s  = c & (NSTAGE - 1);
        const int ph = (c >> 2) & 1;
        mbar_wait(s2u(&mbar[s]), ph);

#pragma unroll
        for (int j = 0; j < VPT; j++) {
            float4 v = stage[s][tid + j * THREADS];
            unsigned long long p01, p23;
            asm("mov.b64 %0, {%1,%2};" : "=l"(p01) : "f"(v.x), "f"(v.y));
            asm("mov.b64 %0, {%1,%2};" : "=l"(p23) : "f"(v.z), "f"(v.w));
            asm("fma.rn.f32x2 %0, %1, %1, %0;" : "+l"(ssA) : "l"(p01));
            asm("fma.rn.f32x2 %0, %1, %1, %0;" : "+l"(ssB) : "l"(p23));
            mx0 = fmaxf(mx0, fmaxf(v.x, v.y));
            mx1 = fmaxf(mx1, fmaxf(v.z, v.w));
        }
        __syncthreads();                        // stage s fully consumed
        if (tid == 0 && c + NSTAGE < NCHUNK) {  // refill
            mbar_expect_tx(s2u(&mbar[s]), CHUNK_BYTES);
            bulk_g2s(s2u(&stage[s][0]), rowp + (c + NSTAGE) * CHUNK_FLOATS,
                     CHUNK_BYTES, s2u(&mbar[s]));
        }
    }

    float sa0, sa1, sb0, sb1;
    asm("mov.b64 {%0,%1}, %2;" : "=f"(sa0), "=f"(sa1) : "l"(ssA));
    asm("mov.b64 {%0,%1}, %2;" : "=f"(sb0), "=f"(sb1) : "l"(ssB));
    float ssv = (sa0 + sa1) + (sb0 + sb1);

    const unsigned key = f2ord(fmaxf(mx0, mx1));

    // ---- warp reduce: sum(ss) and top-2 of thread-max keys ----------------
    unsigned k1 = key, k2 = 0u;
#pragma unroll
    for (int off = 16; off > 0; off >>= 1) {
        ssv += __shfl_xor_sync(0xFFFFFFFFu, ssv, off);
        unsigned o1 = __shfl_xor_sync(0xFFFFFFFFu, k1, off);
        unsigned o2 = __shfl_xor_sync(0xFFFFFFFFu, k2, off);
        unsigned hi = max(k1, o1);
        unsigned se = max(min(k1, o1), max(k2, o2));
        k1 = hi; k2 = se;
    }

    if (lane == 0) { wss[wid] = ssv; w2nd[wid] = k2; }
    __syncthreads();   // barrier #1

    // tau = min over warps of (warp's 2nd-largest thread-max)
    // => >=2 elements per warp >= tau => >=16 elements >= tau (exactness)
    unsigned tau_ord = w2nd[0];
    float tot = wss[0];
#pragma unroll
    for (int w = 1; w < NWARP; w++) {
        tau_ord = min(tau_ord, w2nd[w]);
        tot += wss[w];
    }
    const float tau   = ord2f(tau_ord);
    const float scale = rsqrtf(fmaxf(tot, 1e-12f));

    // ---------------- Phase B: sparse rescan (L2-hot) ----------------------
    if (key >= tau_ord) {          // ~35 of 256 threads
        const float4* __restrict__ xp = reinterpret_cast<const float4*>(rowp);
#pragma unroll
        for (int it = 0; it < HW / 4 / THREADS; it++) {
            float4 v = xp[tid + it * THREADS];
            int base = (tid + it * THREADS) * 4;
#pragma unroll
            for (int e = 0; e < 4; e++) {
                float f = (e == 0) ? v.x : (e == 1) ? v.y : (e == 2) ? v.z : v.w;
                if (f >= tau) {
                    unsigned long long kk =
                        ((unsigned long long)f2ord(f) << 32) |
                        (unsigned)(~(unsigned)(base + e));
                    int pos = atomicAdd(&ccnt, 1);
                    if (pos < CAP) cand_s[pos] = kk;
                }
            }
        }
    }
    __syncthreads();   // barrier #2

    // ---------------- parallel rank-select + write -------------------------
    const int C = min(ccnt, CAP);   // >= 16 guaranteed
    for (int i = tid; i < C; i += THREADS) {
        unsigned long long mine = cand_s[i];
        int rank = 0;
        for (int j = 0; j < C; j++)
            rank += (cand_s[j] > mine);   // keys unique (index embedded)
        if (rank < KTOP) {
            float val = ord2f((unsigned)(mine >> 32)) * scale;
            int idx = (int)(~(unsigned)(mine & 0xFFFFFFFFull));
            out_val[(size_t)row * KTOP + rank] = val;
            out_coor[(size_t)row * KTOP + rank] =
                make_float2((float)(idx >> 7), (float)(idx & (WDIM - 1)));
        }
    }
}

extern "C" void kernel_launch(void* const* d_in, const int* in_sizes, int n_in,
                              void* d_out, int out_size)
{
    const float* x = (const float*)d_in[0];
    int n = in_sizes[0];               // 16*256*128*128
    int rows = n / HW;                 // 4096

    float*  out_val  = (float*)d_out;
    float2* out_coor = (float2*)(out_val + (size_t)rows * KTOP);

    topk_l2_kernel<<<rows, THREADS>>>(x, out_val, out_coor);
}